// round 13
// baseline (speedup 1.0000x reference)
#include <cuda_runtime.h>
#include <math.h>
#include <stdint.h>

// Round 9: rounds 2/7/8 tied (~2150us) across three compute engines =>
// k_knn was smem-crossbar-bound, not compute-bound. Root cause: 32B lane
// stride on column LDS.128 (2-way conflict) + 8 row broadcasts/c-step.
// Fix: 16B-stride conflict-free col ownership + paired (v,v,v',v') row
// broadcasts => crossbar 12 cyc/warp-c-step < compute. Norms folded into
// k_knn; k_knn launched FIRST so ncu captures it next round.

#define NB 4
#define NC 64
#define NN 8192
#define NO 128
#define KK 20

// ---------------- scratch (device globals: allocation-free) ----------------
__device__ float g_xt[NB * NN * NC];   // x transposed: [b][n][c] (for k_mlp)
__device__ int   g_idx[NB * NN * KK];  // top-K neighbor sets (unsorted)

// ---------------- f32x2 helpers ----------------
__device__ __forceinline__ unsigned long long pk2(float a, float b) {
    unsigned long long r;
    asm("mov.b64 %0, {%1, %2};" : "=l"(r) : "f"(a), "f"(b));
    return r;
}
__device__ __forceinline__ void upk2(float& a, float& b, unsigned long long v) {
    asm("mov.b64 {%0, %1}, %2;" : "=f"(a), "=f"(b) : "l"(v));
}
__device__ __forceinline__ void fma2(unsigned long long& d, unsigned long long a,
                                     unsigned long long b) {
    asm("fma.rn.f32x2 %0, %1, %2, %0;" : "+l"(d) : "l"(a), "l"(b));
}
__device__ __forceinline__ unsigned long long mul2(unsigned long long a,
                                                   unsigned long long b) {
    unsigned long long r;
    asm("mul.rn.f32x2 %0, %1, %2;" : "=l"(r) : "l"(a), "l"(b));
    return r;
}

// ============================================================================
// K2 (launched FIRST): FFMA2 distance GEMM + distributed-register top-20.
// CTA = 64 rows (8 warps x 8 rows), col tiles of 256.
// Lane owns cols {4l..4l+3} and {128+4l..+3}  (16B stride: conflict-free).
// Rows stored as float4 (vr,vr,vr1,vr1): one broadcast serves 2 rows.
// pd = dot - 0.5||m||^2 (monotone in reference key => same top-20 set).
// Col norms computed inline during tile load (no dependency on k_prep).
// dyn smem (floats):
//   s_tile [64][260]   @0      (16640)
//   s_rowq [32][65] f4 @16640  (8320)
//   s_ntxx [256]       @24960
//   s_np   [4][64] f4  @25216  (1024)   total 26240 f = 104960 B
// ============================================================================
#define KNN_SMEM (26240 * 4)

__global__ __launch_bounds__(256, 2) void k_knn(const float* __restrict__ x) {
    extern __shared__ float sm[];
    float*  s_tile = sm;                       // [64][260]
    float4* s_rowq = (float4*)(sm + 16640);    // [(r>>1)*65 + c]
    float*  s_ntxx = sm + 24960;               // [256]  -0.5*||m||^2
    float4* s_np   = (float4*)(sm + 25216);    // [4][64] norm partials

    int tid = threadIdx.x, lane = tid & 31, w = tid >> 5;
    int b = blockIdx.y;
    int r0 = blockIdx.x * 64;
    const float* xb = x + (size_t)b * NC * NN;

    // rows, duplicated+paired: s_rowq[r2][c] = (v_{2r2}, v_{2r2}, v_{2r2+1}, v_{2r2+1})
    for (int i = tid; i < 64 * 64; i += 256) {
        int r = i & 63, c = i >> 6;
        float v = xb[c * NN + r0 + r];
        float* dst = (float*)&s_rowq[(r >> 1) * 65 + c] + (r & 1) * 2;
        dst[0] = v; dst[1] = v;
    }

    // distributed top-20 state: lane e<20 holds entry e of each of 8 rows
    float val[8], rmin[8]; int idxr[8];
    #pragma unroll
    for (int j = 0; j < 8; j++) {
        val[j] = (lane < KK) ? -INFINITY : INFINITY;
        idxr[j] = 0;
        rmin[j] = -INFINITY;
    }

    for (int m0 = 0; m0 < NN; m0 += 256) {
        __syncthreads();
        // tile load + inline column-norm partials (thread owns col group tid&63)
        float4 np = make_float4(0.f, 0.f, 0.f, 0.f);
        #pragma unroll 4
        for (int t = 0; t < 16; t++) {
            int i = tid + 256 * t;
            int c = i >> 6, m4 = i & 63;
            float4 v = *(const float4*)&xb[c * NN + m0 + 4 * m4];
            *(float4*)&s_tile[c * 260 + 4 * m4] = v;
            np.x += v.x * v.x; np.y += v.y * v.y;
            np.z += v.z * v.z; np.w += v.w * v.w;
        }
        s_np[(tid >> 6) * 64 + (tid & 63)] = np;
        __syncthreads();
        if (tid < 64) {
            float4 a = s_np[tid], b4 = s_np[64 + tid];
            float4 c4 = s_np[128 + tid], d4 = s_np[192 + tid];
            float4 s;
            s.x = -0.5f * (a.x + b4.x + c4.x + d4.x);
            s.y = -0.5f * (a.y + b4.y + c4.y + d4.y);
            s.z = -0.5f * (a.z + b4.z + c4.z + d4.z);
            s.w = -0.5f * (a.w + b4.w + c4.w + d4.w);
            *(float4*)&s_ntxx[4 * tid] = s;
        }
        __syncthreads();

        // accumulate: 8 rows x (4+4 cols) per lane
        unsigned long long acc[8][4];
        #pragma unroll
        for (int j = 0; j < 8; j++)
            #pragma unroll
            for (int p = 0; p < 4; p++) acc[j][p] = 0ull;

        #pragma unroll 2
        for (int c = 0; c < 64; c++) {
            const ulonglong2 ca = *(const ulonglong2*)&s_tile[c * 260 + 4 * lane];
            const ulonglong2 cb = *(const ulonglong2*)&s_tile[c * 260 + 128 + 4 * lane];
            #pragma unroll
            for (int j2 = 0; j2 < 4; j2++) {
                const ulonglong2 rq = *(const ulonglong2*)&s_rowq[(4 * w + j2) * 65 + c];
                fma2(acc[2*j2][0],   rq.x, ca.x); fma2(acc[2*j2][1],   rq.x, ca.y);
                fma2(acc[2*j2][2],   rq.x, cb.x); fma2(acc[2*j2][3],   rq.x, cb.y);
                fma2(acc[2*j2+1][0], rq.y, ca.x); fma2(acc[2*j2+1][1], rq.y, ca.y);
                fma2(acc[2*j2+1][2], rq.y, cb.x); fma2(acc[2*j2+1][3], rq.y, cb.y);
            }
        }

        // selection (lane's cols: q<4 -> 4l+q ; q>=4 -> 128+4l+(q-4))
        float4 na = *(const float4*)&s_ntxx[4 * lane];
        float4 nb = *(const float4*)&s_ntxx[128 + 4 * lane];
        #pragma unroll
        for (int j = 0; j < 8; j++) {
            float pd[8];
            {
                float a0, a1;
                upk2(a0, a1, acc[j][0]); pd[0] = a0 + na.x; pd[1] = a1 + na.y;
                upk2(a0, a1, acc[j][1]); pd[2] = a0 + na.z; pd[3] = a1 + na.w;
                upk2(a0, a1, acc[j][2]); pd[4] = a0 + nb.x; pd[5] = a1 + nb.y;
                upk2(a0, a1, acc[j][3]); pd[6] = a0 + nb.z; pd[7] = a1 + nb.w;
            }
            float lmax = pd[0];
            #pragma unroll
            for (int q = 1; q < 8; q++) lmax = fmaxf(lmax, pd[q]);

            unsigned act = __ballot_sync(0xffffffffu, lmax > rmin[j]);
            while (act) {
                int src = __ffs(act) - 1; act &= act - 1;
                #pragma unroll
                for (int q = 0; q < 8; q++) {
                    float v = __shfl_sync(0xffffffffu, pd[q], src);
                    if (v > rmin[j]) {                 // uniform branch
                        unsigned eq = __ballot_sync(0xffffffffu, val[j] == rmin[j]);
                        int sel = __ffs(eq) - 1;
                        int col = (q < 4) ? (4 * src + q) : (128 + 4 * src + q - 4);
                        if (lane == sel) { val[j] = v; idxr[j] = m0 + col; }
                        float mv = val[j];
                        #pragma unroll
                        for (int off = 16; off > 0; off >>= 1)
                            mv = fminf(mv, __shfl_xor_sync(0xffffffffu, mv, off));
                        rmin[j] = mv;
                    }
                }
            }
        }
    }

    if (lane < KK) {
        #pragma unroll
        for (int j = 0; j < 8; j++)
            g_idx[((size_t)b * NN + r0 + 8 * w + j) * KK + lane] = idxr[j];
    }
}

// ============================================================================
// K1: transpose x[b][c][n] -> xt[b][n][c]  (only k_mlp needs it now)
// ============================================================================
__global__ __launch_bounds__(256) void k_prep(const float* __restrict__ x) {
    __shared__ float t[64 * 65];
    int b = blockIdx.y;
    int n0 = blockIdx.x * 64;
    int tid = threadIdx.x;
    const float* xb = x + (size_t)b * NC * NN;

    for (int i = tid; i < 64 * 64; i += 256) {
        int c = i >> 6, nn = i & 63;
        t[c * 65 + nn] = xb[c * NN + n0 + nn];
    }
    __syncthreads();
    for (int i = tid; i < 64 * 64; i += 256) {
        int nn = i >> 6, c = i & 63;
        g_xt[((size_t)b * NN + n0 + nn) * NC + c] = t[c * 65 + nn];
    }
}

// ============================================================================
// K3: per-point gated MLP, FFMA2 (round-8 version, unchanged)
// ============================================================================
#define MLP_SMEM (49152 * 4)

__global__ __launch_bounds__(256) void k_mlp(const float* __restrict__ W1,
                                             const float* __restrict__ W2,
                                             float* __restrict__ out) {
    extern __shared__ float sm[];
    float*  sW1h   = sm;                       // [cin*68 + d]
    float*  sW2    = sm + 8704;                // [c*132 + o]
    float2* sdiffd = (float2*)(sm + 25600);    // [(wid*20+k)*64 + c]
    float2* sxnd   = (float2*)(sm + 46080);    // [wid*64 + c]
    float2* sgd    = (float2*)(sm + 47104);    // [wid*128 + c]

    int tid = threadIdx.x, lane = tid & 31, wid = tid >> 5;

    for (int i = tid; i < 64 * 128; i += 256) {
        int d = i >> 7, c = i & 127;
        sW1h[c * 68 + d] = W1[i];
    }
    for (int i = tid; i < 128 * 128; i += 256) {
        int o = i >> 7, c = i & 127;
        sW2[c * 132 + o] = W2[i];
    }
    __syncthreads();

    float2* dif2 = sdiffd + wid * 20 * 64;

    int gw = blockIdx.x * 8 + wid;
    for (int p = gw; p < NB * NN; p += 148 * 8) {
        int b = p >> 13, n = p & (NN - 1);
        const float* xc = g_xt + (size_t)p * 64;
        float xn0 = xc[lane], xn1 = xc[lane + 32];
        sxnd[wid * 64 + lane]      = make_float2(xn0, xn0);
        sxnd[wid * 64 + lane + 32] = make_float2(xn1, xn1);

        int midx = 0;
        if (lane < KK) midx = g_idx[p * KK + lane];
        #pragma unroll
        for (int k = 0; k < KK; k++) {
            int m = __shfl_sync(0xffffffffu, midx, k);
            const float* xm = g_xt + ((size_t)b * NN + m) * 64;
            float d0 = xm[lane]      - xn0;
            float d1 = xm[lane + 32] - xn1;
            dif2[k * 64 + lane]      = make_float2(d0, d0);
            dif2[k * 64 + lane + 32] = make_float2(d1, d1);
        }
        __syncwarp();

        // h for d = (2l, 2l+1) packed; FFMA2 over c
        unsigned long long h01[KK];
        #pragma unroll
        for (int k = 0; k < KK; k++) h01[k] = 0ull;
        unsigned long long hc = 0ull;
        #pragma unroll 2
        for (int c = 0; c < 64; c++) {
            unsigned long long wa  = *(const unsigned long long*)&sW1h[c * 68 + 2 * lane];
            unsigned long long wb  = *(const unsigned long long*)&sW1h[(64 + c) * 68 + 2 * lane];
            unsigned long long xc2 = *(const unsigned long long*)&sxnd[wid * 64 + c];
            fma2(hc, xc2, wb);
            #pragma unroll
            for (int k = 0; k < KK; k++) {
                unsigned long long dd = *(const unsigned long long*)&dif2[k * 64 + c];
                fma2(h01[k], dd, wa);
            }
        }
        float hcx, hcy;
        upk2(hcx, hcy, hc);
        float h0[KK], h1[KK];
        float m0v = -INFINITY, m1v = -INFINITY;
        #pragma unroll
        for (int k = 0; k < KK; k++) {
            upk2(h0[k], h1[k], h01[k]);
            h0[k] += hcx; h1[k] += hcy;
            m0v = fmaxf(m0v, h0[k]); m1v = fmaxf(m1v, h1[k]);
        }
        float s0 = 0.f, s1 = 0.f;
        #pragma unroll
        for (int k = 0; k < KK; k++) {
            h0[k] = __expf(h0[k] - m0v); s0 += h0[k];
            h1[k] = __expf(h1[k] - m1v); s1 += h1[k];
        }
        float i0 = 1.f / s0, i1 = 1.f / s1;

        unsigned long long ga2 = 0ull;
        #pragma unroll
        for (int k = 0; k < KK; k++) {
            ulonglong2 dp = *(const ulonglong2*)&dif2[k * 64 + 2 * lane];
            float d0, d1, t;
            upk2(d0, t, dp.x);
            upk2(d1, t, dp.y);
            fma2(ga2, pk2(d0, d1), pk2(h0[k], h1[k]));
        }
        ga2 = mul2(ga2, pk2(i0, i1));
        float ga0, ga1;
        upk2(ga0, ga1, ga2);

        sgd[wid * 128 + 2 * lane]     = make_float2(ga0, ga0);
        sgd[wid * 128 + 2 * lane + 1] = make_float2(ga1, ga1);
        sgd[wid * 128 + 64 + lane]    = make_float2(xn0, xn0);  // center half
        sgd[wid * 128 + 96 + lane]    = make_float2(xn1, xn1);
        __syncwarp();

        unsigned long long o01 = 0ull, o23 = 0ull;
        const float2* gpd = sgd + wid * 128;
        #pragma unroll 4
        for (int c = 0; c < 128; c++) {
            unsigned long long gv = *(const unsigned long long*)&gpd[c];
            ulonglong2 wp = *(const ulonglong2*)&sW2[c * 132 + 4 * lane];
            fma2(o01, gv, wp.x);
            fma2(o23, gv, wp.y);
        }
        float o0, o1, o2, o3;
        upk2(o0, o1, o01);
        upk2(o2, o3, o23);
        float* op = out + (size_t)b * NO * NN + n;
        op[(4 * lane + 0) * NN] = o0;
        op[(4 * lane + 1) * NN] = o1;
        op[(4 * lane + 2) * NN] = o2;
        op[(4 * lane + 3) * NN] = o3;
        __syncwarp();
    }
}

// ============================================================================
extern "C" void kernel_launch(void* const* d_in, const int* in_sizes, int n_in,
                              void* d_out, int out_size) {
    const float* x  = (const float*)d_in[0];
    const float* W1 = (const float*)d_in[1];
    const float* W2 = (const float*)d_in[2];
    float* out = (float*)d_out;

    cudaFuncSetAttribute(k_knn, cudaFuncAttributeMaxDynamicSharedMemorySize, KNN_SMEM);
    cudaFuncSetAttribute(k_mlp, cudaFuncAttributeMaxDynamicSharedMemorySize, MLP_SMEM);

    dim3 g2(NN / 64, NB);
    k_knn<<<g2, 256, KNN_SMEM>>>(x);     // first: ncu -s 5 should land here
    dim3 g1(NN / 64, NB);
    k_prep<<<g1, 256>>>(x);
    k_mlp<<<148, 256, MLP_SMEM>>>(W1, W2, out);
}

// round 14
// speedup vs baseline: 1.9067x; 1.9067x over previous
#include <cuda_runtime.h>
#include <math.h>
#include <stdint.h>

// Round 14: round-9 regression root-caused as REGISTER SPILLS (regs=128 at
// cap, L1=35% local traffic): 8x8 packed accumulators + selection state
// overflowed the RF. Fix: 8 rows x 4 cols blocking (acc=32 regs, ~85 total,
// no spill), 66KB smem -> 2 CTAs/SM; norms back in k_prep (no per-tile
// barriers). k_mlp occupancy doubled: 512-thread CTAs, 16 warps/SM.

#define NB 4
#define NC 64
#define NN 8192
#define NO 128
#define KK 20

// ---------------- scratch (device globals: allocation-free) ----------------
__device__ float g_xt[NB * NN * NC];   // x transposed: [b][n][c]
__device__ float g_ntxxh[NB * NN];     // -0.5 * ||x||^2
__device__ int   g_idx[NB * NN * KK];  // top-K neighbor sets (unsorted)

// ---------------- f32x2 helpers ----------------
__device__ __forceinline__ void upk2(float& a, float& b, unsigned long long v) {
    asm("mov.b64 {%0, %1}, %2;" : "=f"(a), "=f"(b) : "l"(v));
}
__device__ __forceinline__ void fma2(unsigned long long& d, unsigned long long a,
                                     unsigned long long b) {
    asm("fma.rn.f32x2 %0, %1, %2, %0;" : "+l"(d) : "l"(a), "l"(b));
}

// ============================================================================
// K1: transpose x[b][c][n] -> xt[b][n][c], and ntxxh = -0.5*sum_c x^2
// ============================================================================
__global__ __launch_bounds__(256) void k_prep(const float* __restrict__ x) {
    __shared__ float t[64 * 65];
    int b = blockIdx.y;
    int n0 = blockIdx.x * 64;
    int tid = threadIdx.x;
    const float* xb = x + (size_t)b * NC * NN;

    for (int i = tid; i < 64 * 64; i += 256) {
        int c = i >> 6, nn = i & 63;
        t[c * 65 + nn] = xb[c * NN + n0 + nn];
    }
    __syncthreads();
    for (int i = tid; i < 64 * 64; i += 256) {
        int nn = i >> 6, c = i & 63;
        g_xt[((size_t)b * NN + n0 + nn) * NC + c] = t[c * 65 + nn];
    }
    if (tid < 64) {
        float s = 0.f;
        #pragma unroll
        for (int c = 0; c < 64; c++) { float v = t[c * 65 + tid]; s += v * v; }
        g_ntxxh[b * NN + n0 + tid] = -0.5f * s;
    }
}

// ============================================================================
// K2: FFMA2 distance GEMM + distributed-register top-20.
// CTA = 64 rows (8 warps x 8 rows), col tiles of 128; lane owns cols
// 4l..4l+3 (one LDS.128, conflict-free). Rows stored paired (v,v,v',v'):
// one 16B broadcast feeds 2 rows. acc = 8x2 u64 = 32 regs -> NO SPILLS.
// pd = dot - 0.5||m||^2 (monotone in reference key => same top-20 set).
// dyn smem (floats): s_tile[64][132] @0 (8448) | s_rowq[32][65]f4 @8448
// (8320) | s_ntxx[128] @16768   total 16896 f = 67584 B -> 2 CTAs/SM.
// ============================================================================
#define KNN_SMEM (16896 * 4)

__global__ __launch_bounds__(256, 2) void k_knn(const float* __restrict__ x) {
    extern __shared__ float sm[];
    float*  s_tile = sm;                      // [64][132]
    float4* s_rowq = (float4*)(sm + 8448);    // [(r>>1)*65 + c] = (vr,vr,vr1,vr1)
    float*  s_ntxx = sm + 16768;              // [128]

    int tid = threadIdx.x, lane = tid & 31, w = tid >> 5;
    int b = blockIdx.y;
    int r0 = blockIdx.x * 64;
    const float* xb = x + (size_t)b * NC * NN;

    // rows, duplicated+paired
    for (int i = tid; i < 64 * 64; i += 256) {
        int r = i & 63, c = i >> 6;
        float v = xb[c * NN + r0 + r];
        float* dst = (float*)&s_rowq[(r >> 1) * 65 + c] + (r & 1) * 2;
        dst[0] = v; dst[1] = v;
    }

    // distributed top-20 state: lane e<20 holds entry e of each of 8 rows
    float val[8], rmin[8]; int idxr[8];
    #pragma unroll
    for (int j = 0; j < 8; j++) {
        val[j] = (lane < KK) ? -INFINITY : INFINITY;
        idxr[j] = 0;
        rmin[j] = -INFINITY;
    }

    for (int m0 = 0; m0 < NN; m0 += 128) {
        __syncthreads();
        #pragma unroll
        for (int t = 0; t < 8; t++) {
            int i = tid + 256 * t;
            int c = i >> 5, m4 = i & 31;
            *(float4*)&s_tile[c * 132 + 4 * m4] =
                *(const float4*)&xb[c * NN + m0 + 4 * m4];
        }
        if (tid < 128) s_ntxx[tid] = g_ntxxh[b * NN + m0 + tid];
        __syncthreads();

        // accumulate: 8 rows x 4 cols per lane (cols 4l..4l+3)
        unsigned long long acc[8][2];
        #pragma unroll
        for (int j = 0; j < 8; j++) { acc[j][0] = 0ull; acc[j][1] = 0ull; }

        #pragma unroll 4
        for (int c = 0; c < 64; c++) {
            const ulonglong2 ca = *(const ulonglong2*)&s_tile[c * 132 + 4 * lane];
            #pragma unroll
            for (int j2 = 0; j2 < 4; j2++) {
                const ulonglong2 rq = *(const ulonglong2*)&s_rowq[(4 * w + j2) * 65 + c];
                fma2(acc[2*j2][0],   rq.x, ca.x); fma2(acc[2*j2][1],   rq.x, ca.y);
                fma2(acc[2*j2+1][0], rq.y, ca.x); fma2(acc[2*j2+1][1], rq.y, ca.y);
            }
        }

        // selection: lane's cols 4l+q
        const float4 na = *(const float4*)&s_ntxx[4 * lane];
        #pragma unroll
        for (int j = 0; j < 8; j++) {
            float pd[4];
            {
                float a0, a1;
                upk2(a0, a1, acc[j][0]); pd[0] = a0 + na.x; pd[1] = a1 + na.y;
                upk2(a0, a1, acc[j][1]); pd[2] = a0 + na.z; pd[3] = a1 + na.w;
            }
            float lmax = fmaxf(fmaxf(pd[0], pd[1]), fmaxf(pd[2], pd[3]));

            unsigned act = __ballot_sync(0xffffffffu, lmax > rmin[j]);
            while (act) {
                int src = __ffs(act) - 1; act &= act - 1;
                #pragma unroll
                for (int q = 0; q < 4; q++) {
                    float v = __shfl_sync(0xffffffffu, pd[q], src);
                    if (v > rmin[j]) {                 // uniform branch
                        unsigned eq = __ballot_sync(0xffffffffu, val[j] == rmin[j]);
                        int sel = __ffs(eq) - 1;
                        if (lane == sel) { val[j] = v; idxr[j] = m0 + 4 * src + q; }
                        float mv = val[j];
                        #pragma unroll
                        for (int off = 16; off > 0; off >>= 1)
                            mv = fminf(mv, __shfl_xor_sync(0xffffffffu, mv, off));
                        rmin[j] = mv;
                    }
                }
            }
        }
    }

    if (lane < KK) {
        #pragma unroll
        for (int j = 0; j < 8; j++)
            g_idx[((size_t)b * NN + r0 + 8 * w + j) * KK + lane] = idxr[j];
    }
}

// ============================================================================
// K3: per-point gated MLP. 512 threads (16 warps) per CTA for occupancy;
// warp per point; round-2 proven scalar/float2 math.
// softmax over k sums to 1 => center half of gated feats = x_n exactly;
// only h[:, d<64] needed.
// dyn smem (floats):
//   sW1h [128][68]   @0      sW1h[cin][d], d<64
//   sW2  [128][132]  @8704   sW2[c][o]
//   sdiff[16][20][64]@25600  (20480)
//   sxn  [16][64]    @46080
//   sg   [16][128]   @47104  total 49152 f = 196608 B
// ============================================================================
#define MLP_SMEM (49152 * 4)
#define MLP_THREADS 512
#define MLP_WARPS 16

__global__ __launch_bounds__(MLP_THREADS) void k_mlp(const float* __restrict__ W1,
                                                     const float* __restrict__ W2,
                                                     float* __restrict__ out) {
    extern __shared__ float sm[];
    float* sW1h  = sm;               // [cin*68 + d]
    float* sW2   = sm + 8704;        // [c*132 + o]
    float* sdiff = sm + 25600;       // [(wid*20+k)*64 + c]
    float* sxn   = sm + 46080;       // [wid*64 + c]
    float* sg    = sm + 47104;       // [wid*128 + c]

    int tid = threadIdx.x, lane = tid & 31, wid = tid >> 5;

    for (int i = tid; i < 64 * 128; i += MLP_THREADS) {
        int d = i >> 7, c = i & 127;
        sW1h[c * 68 + d] = W1[i];
    }
    for (int i = tid; i < 128 * 128; i += MLP_THREADS) {
        int o = i >> 7, c = i & 127;
        sW2[c * 132 + o] = W2[i];
    }
    __syncthreads();

    const float* dif = sdiff + wid * 20 * 64;

    int gw = blockIdx.x * MLP_WARPS + wid;
    for (int p = gw; p < NB * NN; p += 148 * MLP_WARPS) {
        int b = p >> 13, n = p & (NN - 1);
        const float* xc = g_xt + (size_t)p * 64;
        float xn0 = xc[lane], xn1 = xc[lane + 32];
        sxn[wid * 64 + lane] = xn0;
        sxn[wid * 64 + lane + 32] = xn1;

        int midx = 0;
        if (lane < KK) midx = g_idx[p * KK + lane];
        #pragma unroll
        for (int k = 0; k < KK; k++) {
            int m = __shfl_sync(0xffffffffu, midx, k);
            const float* xm = g_xt + ((size_t)b * NN + m) * 64;
            sdiff[(wid * 20 + k) * 64 + lane]      = xm[lane]      - xn0;
            sdiff[(wid * 20 + k) * 64 + lane + 32] = xm[lane + 32] - xn1;
        }
        __syncwarp();

        // h for d = 2*lane, 2*lane+1 ; float2 over c
        float h0[KK], h1[KK];
        #pragma unroll
        for (int k = 0; k < KK; k++) { h0[k] = 0.f; h1[k] = 0.f; }
        float hc0 = 0.f, hc1 = 0.f;
        #pragma unroll 2
        for (int c2 = 0; c2 < 32; c2++) {
            int c = 2 * c2;
            const float2 wa0 = *(const float2*)&sW1h[c * 68 + 2 * lane];
            const float2 wa1 = *(const float2*)&sW1h[(c + 1) * 68 + 2 * lane];
            const float2 wb0 = *(const float2*)&sW1h[(64 + c) * 68 + 2 * lane];
            const float2 wb1 = *(const float2*)&sW1h[(65 + c) * 68 + 2 * lane];
            const float2 xnc = *(const float2*)&sxn[wid * 64 + c];
            hc0 += xnc.x * wb0.x + xnc.y * wb1.x;
            hc1 += xnc.x * wb0.y + xnc.y * wb1.y;
            #pragma unroll
            for (int k = 0; k < KK; k++) {
                const float2 dv = *(const float2*)&dif[k * 64 + c];
                h0[k] += dv.x * wa0.x + dv.y * wa1.x;
                h1[k] += dv.x * wa0.y + dv.y * wa1.y;
            }
        }
        // softmax over k (two d-columns per lane)
        float m0v = -INFINITY, m1v = -INFINITY;
        #pragma unroll
        for (int k = 0; k < KK; k++) {
            h0[k] += hc0; h1[k] += hc1;
            m0v = fmaxf(m0v, h0[k]); m1v = fmaxf(m1v, h1[k]);
        }
        float s0 = 0.f, s1 = 0.f;
        #pragma unroll
        for (int k = 0; k < KK; k++) {
            h0[k] = __expf(h0[k] - m0v); s0 += h0[k];
            h1[k] = __expf(h1[k] - m1v); s1 += h1[k];
        }
        float i0 = 1.f / s0, i1 = 1.f / s1;

        // gA for c = 2*lane, 2*lane+1
        float ga = 0.f, gb = 0.f;
        #pragma unroll
        for (int k = 0; k < KK; k++) {
            const float2 dv = *(const float2*)&dif[k * 64 + 2 * lane];
            ga += dv.x * h0[k]; gb += dv.y * h1[k];
        }
        float* gp = sg + wid * 128;
        gp[2 * lane]     = ga * i0;
        gp[2 * lane + 1] = gb * i1;
        gp[64 + lane]    = xn0;      // center half: softmax sums to 1
        gp[96 + lane]    = xn1;
        __syncwarp();

        // out[o] = sum_c W2[o][c] * g[c] ; lane owns o = 4*lane..+3
        float o0 = 0.f, o1 = 0.f, o2 = 0.f, o3 = 0.f;
        #pragma unroll 4
        for (int c = 0; c < 128; c++) {
            float gv = gp[c];
            const float4 wv = *(const float4*)&sW2[c * 132 + 4 * lane];
            o0 += gv * wv.x; o1 += gv * wv.y; o2 += gv * wv.z; o3 += gv * wv.w;
        }
        float* op = out + (size_t)b * NO * NN + n;
        op[(4 * lane + 0) * NN] = o0;
        op[(4 * lane + 1) * NN] = o1;
        op[(4 * lane + 2) * NN] = o2;
        op[(4 * lane + 3) * NN] = o3;
        __syncwarp();
    }
}

// ============================================================================
extern "C" void kernel_launch(void* const* d_in, const int* in_sizes, int n_in,
                              void* d_out, int out_size) {
    const float* x  = (const float*)d_in[0];
    const float* W1 = (const float*)d_in[1];
    const float* W2 = (const float*)d_in[2];
    float* out = (float*)d_out;

    cudaFuncSetAttribute(k_knn, cudaFuncAttributeMaxDynamicSharedMemorySize, KNN_SMEM);
    cudaFuncSetAttribute(k_mlp, cudaFuncAttributeMaxDynamicSharedMemorySize, MLP_SMEM);

    dim3 g1(NN / 64, NB);
    k_prep<<<g1, 256>>>(x);
    dim3 g2(NN / 64, NB);
    k_knn<<<g2, 256, KNN_SMEM>>>(x);
    k_mlp<<<148, MLP_THREADS, MLP_SMEM>>>(W1, W2, out);
}

// round 16
// speedup vs baseline: 2.5607x; 1.3430x over previous
#include <cuda_runtime.h>
#include <cuda_bf16.h>
#include <math.h>
#include <stdint.h>

// Round 16: r15 crashed on misaligned address — sD stride was 69 floats
// (odd) so float2 accesses at odd rows/groups were 4B-aligned only.
// Fix: stride 70 (even, conflict-acceptable). Everything else unchanged:
// spill-free HMMA mainloop (acc 32 regs, af 32 regs), smem-parked top-20
// state, r14-proven k_mlp.

#define NB 4
#define NC 64
#define NN 8192
#define NO 128
#define KK 20

// ---------------- scratch (device globals: allocation-free) ----------------
__device__ float g_xt[NB * NN * NC];            // x transposed fp32 (k_mlp)
__device__ float g_ntxxh[NB * NN];              // -0.5 * ||x||^2
__device__ int   g_idx[NB * NN * KK];           // top-K sets (unsorted)
__device__ __nv_bfloat16 g_xh[NB * NN * NC];    // bf16 hi
__device__ __nv_bfloat16 g_xl[NB * NN * NC];    // bf16 lo (x - hi)

// ============================================================================
// K1: transpose + norms + bf16 hi/lo split
// ============================================================================
__global__ __launch_bounds__(256) void k_prep(const float* __restrict__ x) {
    __shared__ float t[64 * 65];
    int b = blockIdx.y;
    int n0 = blockIdx.x * 64;
    int tid = threadIdx.x;
    const float* xb = x + (size_t)b * NC * NN;

    for (int i = tid; i < 64 * 64; i += 256) {
        int c = i >> 6, nn = i & 63;
        t[c * 65 + nn] = xb[c * NN + n0 + nn];
    }
    __syncthreads();
    for (int i = tid; i < 64 * 64; i += 256) {
        int nn = i >> 6, c = i & 63;
        float v = t[c * 65 + nn];
        size_t o = ((size_t)b * NN + n0 + nn) * NC + c;
        g_xt[o] = v;
        __nv_bfloat16 h = __float2bfloat16(v);
        g_xh[o] = h;
        g_xl[o] = __float2bfloat16(v - __bfloat162float(h));
    }
    if (tid < 64) {
        float s = 0.f;
        #pragma unroll
        for (int c = 0; c < 64; c++) { float v = t[c * 65 + tid]; s += v * v; }
        g_ntxxh[b * NN + n0 + tid] = -0.5f * s;
    }
}

// ============================================================================
// K2: HMMA KNN, spill-free. CTA = 128 rows (8 warps x m16), 128 col-tiles
// of 64. dot = hi*hi + hi*lo + lo*hi (fp32 accum, mma.sync m16n8k16 bf16).
// acc[8][4]=32 regs, af[8][4]=32 regs. Top-20 state (val/idx/rmin per row)
// lives in smem, loaded/stored per tile. pd = dot - 0.5||m||^2.
// smem (bytes):
//   sA   @0       128 x 136 bf16 = 34816  (hi k0..63, lo k64..127, pad 8)
//   sB   @34816    64 x 136 bf16 = 17408
//   sD   @52224   8w x 16 x 70 f = 35840  (stride 70: EVEN -> f2 aligned)
//   sVal @88064   8w x 16 x 20 f = 10240
//   sIdx @98304   8w x 16 x 20 i = 10240
//   sRmin@108544  8w x 16 f      = 512    total 109056 -> 2 CTAs/SM
// ============================================================================
#define SB_OFF   34816
#define SD_OFF   52224
#define SVAL_OFF 88064
#define SIDX_OFF 98304
#define SRM_OFF  108544
#define KNN_SMEM 109056

__device__ __forceinline__ void mma16816(float* c, const uint32_t* a,
                                         uint32_t b0, uint32_t b1) {
    asm volatile(
        "mma.sync.aligned.m16n8k16.row.col.f32.bf16.bf16.f32 "
        "{%0,%1,%2,%3},{%4,%5,%6,%7},{%8,%9},{%0,%1,%2,%3};"
        : "+f"(c[0]), "+f"(c[1]), "+f"(c[2]), "+f"(c[3])
        : "r"(a[0]), "r"(a[1]), "r"(a[2]), "r"(a[3]), "r"(b0), "r"(b1));
}

__global__ __launch_bounds__(256, 2) void k_knn_mma() {
    extern __shared__ char smem[];
    __nv_bfloat16* sA = (__nv_bfloat16*)smem;
    __nv_bfloat16* sB = (__nv_bfloat16*)(smem + SB_OFF);
    float* sD    = (float*)(smem + SD_OFF);
    float* sVal  = (float*)(smem + SVAL_OFF);
    int*   sIdx  = (int*)(smem + SIDX_OFF);
    float* sRmin = (float*)(smem + SRM_OFF);

    int tid = threadIdx.x, lane = tid & 31, w = tid >> 5;
    int g = lane >> 2, t = lane & 3;
    int b = blockIdx.y;
    int r0 = blockIdx.x * 128;

    // ---- load A block: 128 rows x (hi|lo), stride 136 bf16 ----
    for (int i = tid; i < 128 * 8; i += 256) {
        int r = i >> 3, j = i & 7;
        size_t go = ((size_t)b * NN + r0 + r) * NC + j * 8;
        *(uint4*)&sA[r * 136 + j * 8]      = *(const uint4*)&g_xh[go];
        *(uint4*)&sA[r * 136 + 64 + j * 8] = *(const uint4*)&g_xl[go];
    }
    // ---- init selection state (warp's own 16 rows) ----
    if (lane < KK) {
        #pragma unroll
        for (int r = 0; r < 16; r++) {
            sVal[(w * 16 + r) * 20 + lane] = -INFINITY;
            sIdx[(w * 16 + r) * 20 + lane] = 0;
        }
    }
    if (lane < 16) sRmin[w * 16 + lane] = -INFINITY;
    __syncthreads();

    // ---- cache A fragments: 8 k-steps (0..3 hi, 4..7 lo), 4 regs each ----
    uint32_t af[8][4];
    {
        int arow = 16 * w + g;
        #pragma unroll
        for (int s = 0; s < 8; s++) {
            int koff = 16 * s;
            af[s][0] = *(const uint32_t*)&sA[arow * 136 + koff + 2 * t];
            af[s][1] = *(const uint32_t*)&sA[(arow + 8) * 136 + koff + 2 * t];
            af[s][2] = *(const uint32_t*)&sA[arow * 136 + koff + 8 + 2 * t];
            af[s][3] = *(const uint32_t*)&sA[(arow + 8) * 136 + koff + 8 + 2 * t];
        }
    }

    float* sDw = sD + w * 16 * 70;

    for (int tile = 0; tile < 128; tile++) {
        int m0 = tile * 64;
        __syncthreads();                       // prev tile's sB readers done
        for (int i = tid; i < 64 * 8; i += 256) {
            int r = i >> 3, j = i & 7;
            size_t go = ((size_t)b * NN + m0 + r) * NC + j * 8;
            *(uint4*)&sB[r * 136 + j * 8]      = *(const uint4*)&g_xh[go];
            *(uint4*)&sB[r * 136 + 64 + j * 8] = *(const uint4*)&g_xl[go];
        }
        __syncthreads();

        float acc[8][4];
        #pragma unroll
        for (int nb = 0; nb < 8; nb++)
            #pragma unroll
            for (int q = 0; q < 4; q++) acc[nb][q] = 0.f;

        #pragma unroll
        for (int nb = 0; nb < 8; nb++) {
            const __nv_bfloat16* brow = sB + (nb * 8 + g) * 136 + 2 * t;
            #pragma unroll
            for (int sp = 0; sp < 12; sp++) {
                int afi  = (sp < 4) ? sp : sp - 4;             // hi,hi,lo frags
                int koff = (sp < 8) ? 16 * sp : 16 * (sp - 8); // hiB,loB,hiB
                uint32_t b0 = *(const uint32_t*)&brow[koff];
                uint32_t b1 = *(const uint32_t*)&brow[koff + 8];
                mma16816(acc[nb], af[afi], b0, b1);
            }
        }

        // ---- stage D to per-warp smem tile (stride 70: aligned) ----
        #pragma unroll
        for (int nb = 0; nb < 8; nb++) {
            *(float2*)&sDw[g * 70 + nb * 8 + 2 * t]       = make_float2(acc[nb][0], acc[nb][1]);
            *(float2*)&sDw[(g + 8) * 70 + nb * 8 + 2 * t] = make_float2(acc[nb][2], acc[nb][3]);
        }
        __syncwarp();

        const float2 nt = *(const float2*)&g_ntxxh[(size_t)b * NN + m0 + 2 * lane];

        // ---- selection: 16 rows, state in smem, lane owns cols 2l,2l+1 ----
        #pragma unroll
        for (int r = 0; r < 16; r++) {
            int srow = (w * 16 + r) * 20;
            float val  = (lane < KK) ? sVal[srow + lane] : INFINITY;
            int   idxr = (lane < KK) ? sIdx[srow + lane] : 0;
            float rmin = sRmin[w * 16 + r];

            const float2 dv = *(const float2*)&sDw[r * 70 + 2 * lane];
            float pd0 = dv.x + nt.x, pd1 = dv.y + nt.y;
            float lmax = fmaxf(pd0, pd1);

            unsigned act = __ballot_sync(0xffffffffu, lmax > rmin);
            while (act) {
                int src = __ffs(act) - 1; act &= act - 1;
                #pragma unroll
                for (int q = 0; q < 2; q++) {
                    float v = __shfl_sync(0xffffffffu, q == 0 ? pd0 : pd1, src);
                    if (v > rmin) {                    // uniform branch
                        unsigned eq = __ballot_sync(0xffffffffu, val == rmin);
                        int sel = __ffs(eq) - 1;
                        if (lane == sel) { val = v; idxr = m0 + 2 * src + q; }
                        float mv = val;
                        #pragma unroll
                        for (int off = 16; off > 0; off >>= 1)
                            mv = fminf(mv, __shfl_xor_sync(0xffffffffu, mv, off));
                        rmin = mv;
                    }
                }
            }
            if (lane < KK) { sVal[srow + lane] = val; sIdx[srow + lane] = idxr; }
            if (lane == 0) sRmin[w * 16 + r] = rmin;
        }
    }

    __syncwarp();
    if (lane < KK) {
        #pragma unroll
        for (int r = 0; r < 16; r++)
            g_idx[((size_t)b * NN + r0 + 16 * w + r) * KK + lane] =
                sIdx[(w * 16 + r) * 20 + lane];
    }
}

// ============================================================================
// K3: per-point gated MLP (r14-proven: 512 threads, 16 warps, scalar/float2)
// ============================================================================
#define MLP_SMEM (49152 * 4)
#define MLP_THREADS 512
#define MLP_WARPS 16

__global__ __launch_bounds__(MLP_THREADS) void k_mlp(const float* __restrict__ W1,
                                                     const float* __restrict__ W2,
                                                     float* __restrict__ out) {
    extern __shared__ float sm[];
    float* sW1h  = sm;               // [cin*68 + d]
    float* sW2   = sm + 8704;        // [c*132 + o]
    float* sdiff = sm + 25600;       // [(wid*20+k)*64 + c]
    float* sxn   = sm + 46080;       // [wid*64 + c]
    float* sg    = sm + 47104;       // [wid*128 + c]

    int tid = threadIdx.x, lane = tid & 31, wid = tid >> 5;

    for (int i = tid; i < 64 * 128; i += MLP_THREADS) {
        int d = i >> 7, c = i & 127;
        sW1h[c * 68 + d] = W1[i];
    }
    for (int i = tid; i < 128 * 128; i += MLP_THREADS) {
        int o = i >> 7, c = i & 127;
        sW2[c * 132 + o] = W2[i];
    }
    __syncthreads();

    const float* dif = sdiff + wid * 20 * 64;

    int gw = blockIdx.x * MLP_WARPS + wid;
    for (int p = gw; p < NB * NN; p += 148 * MLP_WARPS) {
        int b = p >> 13, n = p & (NN - 1);
        const float* xc = g_xt + (size_t)p * 64;
        float xn0 = xc[lane], xn1 = xc[lane + 32];
        sxn[wid * 64 + lane] = xn0;
        sxn[wid * 64 + lane + 32] = xn1;

        int midx = 0;
        if (lane < KK) midx = g_idx[p * KK + lane];
        #pragma unroll
        for (int k = 0; k < KK; k++) {
            int m = __shfl_sync(0xffffffffu, midx, k);
            const float* xm = g_xt + ((size_t)b * NN + m) * 64;
            sdiff[(wid * 20 + k) * 64 + lane]      = xm[lane]      - xn0;
            sdiff[(wid * 20 + k) * 64 + lane + 32] = xm[lane + 32] - xn1;
        }
        __syncwarp();

        float h0[KK], h1[KK];
        #pragma unroll
        for (int k = 0; k < KK; k++) { h0[k] = 0.f; h1[k] = 0.f; }
        float hc0 = 0.f, hc1 = 0.f;
        #pragma unroll 2
        for (int c2 = 0; c2 < 32; c2++) {
            int c = 2 * c2;
            const float2 wa0 = *(const float2*)&sW1h[c * 68 + 2 * lane];
            const float2 wa1 = *(const float2*)&sW1h[(c + 1) * 68 + 2 * lane];
            const float2 wb0 = *(const float2*)&sW1h[(64 + c) * 68 + 2 * lane];
            const float2 wb1 = *(const float2*)&sW1h[(65 + c) * 68 + 2 * lane];
            const float2 xnc = *(const float2*)&sxn[wid * 64 + c];
            hc0 += xnc.x * wb0.x + xnc.y * wb1.x;
            hc1 += xnc.x * wb0.y + xnc.y * wb1.y;
            #pragma unroll
            for (int k = 0; k < KK; k++) {
                const float2 dv = *(const float2*)&dif[k * 64 + c];
                h0[k] += dv.x * wa0.x + dv.y * wa1.x;
                h1[k] += dv.x * wa0.y + dv.y * wa1.y;
            }
        }
        float m0v = -INFINITY, m1v = -INFINITY;
        #pragma unroll
        for (int k = 0; k < KK; k++) {
            h0[k] += hc0; h1[k] += hc1;
            m0v = fmaxf(m0v, h0[k]); m1v = fmaxf(m1v, h1[k]);
        }
        float s0 = 0.f, s1 = 0.f;
        #pragma unroll
        for (int k = 0; k < KK; k++) {
            h0[k] = __expf(h0[k] - m0v); s0 += h0[k];
            h1[k] = __expf(h1[k] - m1v); s1 += h1[k];
        }
        float i0 = 1.f / s0, i1 = 1.f / s1;

        float ga = 0.f, gb = 0.f;
        #pragma unroll
        for (int k = 0; k < KK; k++) {
            const float2 dv = *(const float2*)&dif[k * 64 + 2 * lane];
            ga += dv.x * h0[k]; gb += dv.y * h1[k];
        }
        float* gp = sg + wid * 128;
        gp[2 * lane]     = ga * i0;
        gp[2 * lane + 1] = gb * i1;
        gp[64 + lane]    = xn0;      // center half: softmax sums to 1
        gp[96 + lane]    = xn1;
        __syncwarp();

        float o0 = 0.f, o1 = 0.f, o2 = 0.f, o3 = 0.f;
        #pragma unroll 4
        for (int c = 0; c < 128; c++) {
            float gv = gp[c];
            const float4 wv = *(const float4*)&sW2[c * 132 + 4 * lane];
            o0 += gv * wv.x; o1 += gv * wv.y; o2 += gv * wv.z; o3 += gv * wv.w;
        }
        float* op = out + (size_t)b * NO * NN + n;
        op[(4 * lane + 0) * NN] = o0;
        op[(4 * lane + 1) * NN] = o1;
        op[(4 * lane + 2) * NN] = o2;
        op[(4 * lane + 3) * NN] = o3;
        __syncwarp();
    }
}

// ============================================================================
extern "C" void kernel_launch(void* const* d_in, const int* in_sizes, int n_in,
                              void* d_out, int out_size) {
    const float* x  = (const float*)d_in[0];
    const float* W1 = (const float*)d_in[1];
    const float* W2 = (const float*)d_in[2];
    float* out = (float*)d_out;

    cudaFuncSetAttribute(k_knn_mma, cudaFuncAttributeMaxDynamicSharedMemorySize, KNN_SMEM);
    cudaFuncSetAttribute(k_mlp, cudaFuncAttributeMaxDynamicSharedMemorySize, MLP_SMEM);

    dim3 g1(NN / 64, NB);
    k_prep<<<g1, 256>>>(x);
    dim3 g2(NN / 128, NB);
    k_knn_mma<<<g2, 256, KNN_SMEM>>>();
    k_mlp<<<148, MLP_THREADS, MLP_SMEM>>>(W1, W2, out);
}